// round 1
// baseline (speedup 1.0000x reference)
#include <cuda_runtime.h>
#include <math.h>

// Problem constants
#define BB   16
#define CIN  64
#define COUT 64
#define HH   256
#define WW   256
#define MM1  20
#define MM2  20
#define NKX  40          // 2*M1 kx rows kept
#define NMODE 800        // NKX * MM2
#define NBI  1024        // B*CI
#define NBO  1024        // B*CO

// Scratch (static device globals; no runtime allocation)
__device__ float2 g_Xw[NBI * HH * MM2];    // [bi][h][ky]   41.9 MB
__device__ float2 g_Xf[NMODE * NBI];       // [m][bi]        6.6 MB
__device__ float2 g_Yf[NBO * NMODE];       // [bo][m]        6.6 MB
__device__ float2 g_Y [NBO * HH * MM2];    // [bo][h][ky]   41.9 MB

// ---------------------------------------------------------------------------
// Stage 1: DFT along W. Xw[bi,h,ky] = sum_w x[bi,h,w] e^{-2pi i ky w / 256}
// Radix-2 fold: sum_{w<128} (x[w] + (-1)^ky x[w+128]) e^{-i th}, th=2pi ky w/256
// Block = one (b,ci) image. thread: kk=t%10 -> ky pair (2kk,2kk+1), rg=t/10 -> 8 rows
// ---------------------------------------------------------------------------
__global__ void __launch_bounds__(320) stage1_wdft(const float* __restrict__ x) {
    extern __shared__ float smem[];
    float4* tws = (float4*)smem;                 // [128][10]: (c_even,s_even,c_odd,s_odd)
    float2* xs2 = (float2*)(smem + 5120);        // [256][17]: (ue, uo) per (row, wl)

    const int bi = blockIdx.x;
    const int t  = threadIdx.x;

    // Build twiddle table (once per block)
    for (int i = t; i < 1280; i += 320) {
        int w = i / 10, kk = i % 10;
        float s0, c0, s1, c1;
        sincospif((float)((2*kk    ) * w) * (1.0f/128.0f), &s0, &c0);
        sincospif((float)((2*kk + 1) * w) * (1.0f/128.0f), &s1, &c1);
        tws[i] = make_float4(c0, s0, c1, s1);
    }

    const int kk = t % 10;
    const int rg = t / 10;                       // 0..31 -> rows rg*8 .. rg*8+7
    const float* xim = x + (size_t)bi * (HH*WW);

    float aR0[8], aI0[8], aR1[8], aI1[8];
    #pragma unroll
    for (int r = 0; r < 8; r++) { aR0[r]=0.f; aI0[r]=0.f; aR1[r]=0.f; aI1[r]=0.f; }

    for (int c = 0; c < 8; c++) {                // 8 chunks of 16 w (w<128)
        const int w0 = c * 16;
        __syncthreads();                          // (also covers table build at c==0)
        for (int idx = t; idx < 4096; idx += 320) {
            int r  = idx >> 4;
            int wl = idx & 15;
            float a = xim[r*256 + w0 + wl];
            float b = xim[r*256 + w0 + wl + 128];
            xs2[r*17 + wl] = make_float2(a + b, a - b);
        }
        __syncthreads();
        #pragma unroll
        for (int wl = 0; wl < 16; wl++) {
            float4 cs = tws[(w0 + wl)*10 + kk];
            #pragma unroll
            for (int r = 0; r < 8; r++) {
                int row = rg*8 + r;
                float2 u = xs2[row*17 + wl];
                aR0[r] = fmaf( u.x, cs.x, aR0[r]);
                aI0[r] = fmaf(-u.x, cs.y, aI0[r]);
                aR1[r] = fmaf( u.y, cs.z, aR1[r]);
                aI1[r] = fmaf(-u.y, cs.w, aI1[r]);
            }
        }
    }

    float4* outp = (float4*)g_Xw;
    #pragma unroll
    for (int r = 0; r < 8; r++) {
        int row  = rg*8 + r;
        int base = (bi*HH + row)*MM2 + 2*kk;     // float2 index (even -> 16B aligned)
        outp[base >> 1] = make_float4(aR0[r], aI0[r], aR1[r], aI1[r]);
    }
}

// ---------------------------------------------------------------------------
// Stage 2: DFT along H for the 40 kept kx. Xf[m,bi] = sum_h Xw[bi,h,ky] e^{-2pi i kx h/256}
// Block = one (b,ci). thread<400: j=t/10 (kx index), kyp=t%10 (ky pair).
// ---------------------------------------------------------------------------
__global__ void __launch_bounds__(512) stage2_hdft() {
    __shared__ float2 Xws[HH * MM2];   // 40 KB
    __shared__ float2 eb[256];         // e^{+2pi i t/256}

    const int bi = blockIdx.x;
    const int t  = threadIdx.x;

    const float2* src = g_Xw + (size_t)bi * (HH*MM2);
    for (int i = t; i < HH*MM2; i += 512) Xws[i] = src[i];
    if (t < 256) {
        float s, c;
        sincospif((float)t * (1.0f/128.0f), &s, &c);
        eb[t] = make_float2(c, s);
    }
    __syncthreads();

    if (t < 400) {
        const int j   = t / 10;
        const int kyp = t % 10;
        const int kx  = (j < 20) ? j : (216 + j);   // 236 + (j-20)
        const float4* X4 = (const float4*)Xws;

        float4 acc = make_float4(0.f, 0.f, 0.f, 0.f);
        int p = 0;
        for (int h = 0; h < 256; h++) {
            float2 e  = eb[p];                       // e^{+i th}; we need conj
            p = (p + kx) & 255;
            float4 xv = X4[h*10 + kyp];              // (re0,im0,re1,im1)
            acc.x = fmaf(xv.x, e.x, acc.x); acc.x = fmaf( xv.y, e.y, acc.x);
            acc.y = fmaf(xv.y, e.x, acc.y); acc.y = fmaf(-xv.x, e.y, acc.y);
            acc.z = fmaf(xv.z, e.x, acc.z); acc.z = fmaf( xv.w, e.y, acc.z);
            acc.w = fmaf(xv.w, e.x, acc.w); acc.w = fmaf(-xv.z, e.y, acc.w);
        }
        const int m0 = j*20 + 2*kyp;
        g_Xf[(size_t)m0      * NBI + bi] = make_float2(acc.x, acc.y);
        g_Xf[(size_t)(m0+1)  * NBI + bi] = make_float2(acc.z, acc.w);
    }
}

// ---------------------------------------------------------------------------
// Stage 3: channel mix per mode. Yf[bo,m] = sum_i Xf[m, b*64+i] * W[i,o,m]
// Block = one mode m. Weights gathered from raw w1/w2 arrays.
// ---------------------------------------------------------------------------
__global__ void __launch_bounds__(256) stage3_mix(const float* __restrict__ w1re,
                                                 const float* __restrict__ w1im,
                                                 const float* __restrict__ w2re,
                                                 const float* __restrict__ w2im) {
    __shared__ float2 Xs[NBI];        // 8 KB
    __shared__ float2 Ws[CIN*COUT];   // 32 KB

    const int m = blockIdx.x;
    const int t = threadIdx.x;
    const int j = m / 20, ky = m % 20;

    const float* wre; const float* wim; int off;
    if (j < 20) { wre = w1re; wim = w1im; off = j*20 + ky; }
    else        { wre = w2re; wim = w2im; off = (j-20)*20 + ky; }

    for (int i = t; i < NBI; i += 256) Xs[i] = g_Xf[(size_t)m * NBI + i];
    for (int io = t; io < CIN*COUT; io += 256)
        Ws[io] = make_float2(wre[(size_t)io*400 + off], wim[(size_t)io*400 + off]);
    __syncthreads();

    const int o  = t & 63;
    const int xb = (t >> 6) << 6;     // b*64 for k=0
    float2 acc[4];
    #pragma unroll
    for (int k = 0; k < 4; k++) acc[k] = make_float2(0.f, 0.f);

    #pragma unroll 4
    for (int i = 0; i < 64; i++) {
        float2 wv = Ws[i*64 + o];
        #pragma unroll
        for (int k = 0; k < 4; k++) {
            float2 xv = Xs[xb + k*256 + i];
            acc[k].x = fmaf(xv.x, wv.x, acc[k].x); acc[k].x = fmaf(-xv.y, wv.y, acc[k].x);
            acc[k].y = fmaf(xv.x, wv.y, acc[k].y); acc[k].y = fmaf( xv.y, wv.x, acc[k].y);
        }
    }
    #pragma unroll
    for (int k = 0; k < 4; k++)
        g_Yf[(size_t)(t + k*256) * NMODE + m] = acc[k];
}

// ---------------------------------------------------------------------------
// Stage 4: inverse DFT along H. Y[bo,h,ky] = scale(ky) * sum_j Yf[bo,j,ky] e^{+2pi i kx_j h/256}
// scale folds 1/(H*W) and the c2r factor 2 (1x for ky=0). Block = one (b,co).
// ---------------------------------------------------------------------------
__global__ void __launch_bounds__(256) stage4_ihdft() {
    __shared__ float2 Yfs[NMODE];      // 6.4 KB
    __shared__ float2 Ys[HH * MM2];    // 40 KB (staging for coalesced writeout)

    const int bo = blockIdx.x;
    const int t  = threadIdx.x;        // h = t

    for (int i = t; i < NMODE; i += 256) Yfs[i] = g_Yf[(size_t)bo * NMODE + i];
    __syncthreads();

    float2 acc[20];
    #pragma unroll
    for (int k = 0; k < 20; k++) acc[k] = make_float2(0.f, 0.f);

    #pragma unroll 1
    for (int j = 0; j < 40; j++) {
        int kx = (j < 20) ? j : (216 + j);
        int p  = (kx * t) & 255;
        float sn, cs;
        sincospif((float)p * (1.0f/128.0f), &sn, &cs);   // e^{+i th}
        #pragma unroll
        for (int ky = 0; ky < 20; ky++) {
            float2 yf = Yfs[j*20 + ky];
            acc[ky].x = fmaf(yf.x, cs, acc[ky].x); acc[ky].x = fmaf(-yf.y, sn, acc[ky].x);
            acc[ky].y = fmaf(yf.x, sn, acc[ky].y); acc[ky].y = fmaf( yf.y, cs, acc[ky].y);
        }
    }

    const float sc1 = 1.0f / 65536.0f;
    const float sc2 = 2.0f / 65536.0f;
    #pragma unroll
    for (int ky = 0; ky < 20; ky++) {
        float s = (ky == 0) ? sc1 : sc2;
        Ys[t*20 + ky] = make_float2(acc[ky].x * s, acc[ky].y * s);
    }
    __syncthreads();
    for (int i = t; i < HH*MM2; i += 256)
        g_Y[(size_t)bo * (HH*MM2) + i] = Ys[i];
}

// ---------------------------------------------------------------------------
// Stage 5: c2r along W. out[bo,h,w] = sum_ky (Yre*cos - Yim*sin), th=2pi ky w/256
// w/(w+128) symmetry via even/odd-ky partial sums. Block = one (b,co), thread = w<128.
// ---------------------------------------------------------------------------
__global__ void __launch_bounds__(128) stage5_c2r(float* __restrict__ out) {
    __shared__ float2 ys[8 * MM2];     // 8 rows staged

    const int bo = blockIdx.x;
    const int t  = threadIdx.x;        // w in [0,128)

    float cc[20], ns[20];
    #pragma unroll
    for (int ky = 0; ky < 20; ky++) {
        float s, c;
        sincospif((float)(ky * t) * (1.0f/128.0f), &s, &c);
        cc[ky] = c; ns[ky] = -s;
    }

    float* outb = out + (size_t)bo * (HH*WW);
    const float2* ysrc = g_Y + (size_t)bo * (HH*MM2);

    for (int g = 0; g < 32; g++) {
        __syncthreads();
        for (int i = t; i < 8*MM2; i += 128) ys[i] = ysrc[g*(8*MM2) + i];
        __syncthreads();
        const float4* y4 = (const float4*)ys;
        #pragma unroll
        for (int r = 0; r < 8; r++) {
            float ae = 0.f, ao = 0.f;
            #pragma unroll
            for (int kk = 0; kk < 10; kk++) {
                float4 yv = y4[r*10 + kk];         // (re_e, im_e, re_o, im_o) for ky=2kk,2kk+1
                ae = fmaf(yv.x, cc[2*kk  ], ae); ae = fmaf(yv.y, ns[2*kk  ], ae);
                ao = fmaf(yv.z, cc[2*kk+1], ao); ao = fmaf(yv.w, ns[2*kk+1], ao);
            }
            const int h = g*8 + r;
            outb[h*256 + t      ] = ae + ao;
            outb[h*256 + t + 128] = ae - ao;
        }
    }
}

// ---------------------------------------------------------------------------
extern "C" void kernel_launch(void* const* d_in, const int* in_sizes, int n_in,
                              void* d_out, int out_size) {
    const float* x    = (const float*)d_in[0];
    const float* w1re = (const float*)d_in[1];
    const float* w1im = (const float*)d_in[2];
    const float* w2re = (const float*)d_in[3];
    const float* w2im = (const float*)d_in[4];
    float* out = (float*)d_out;

    const int s1_smem = 1280*16 + 256*17*8;   // 20480 + 34816 = 55296 B
    cudaFuncSetAttribute(stage1_wdft, cudaFuncAttributeMaxDynamicSharedMemorySize, s1_smem);

    stage1_wdft <<<NBI, 320, s1_smem>>>(x);
    stage2_hdft <<<NBI, 512>>>();
    stage3_mix  <<<NMODE, 256>>>(w1re, w1im, w2re, w2im);
    stage4_ihdft<<<NBO, 256>>>();
    stage5_c2r  <<<NBO, 128>>>(out);
}

// round 2
// speedup vs baseline: 1.3085x; 1.3085x over previous
#include <cuda_runtime.h>
#include <math.h>

// Problem constants
#define BB   16
#define CIN  64
#define COUT 64
#define HH   256
#define WW   256
#define MM1  20
#define MM2  20
#define NMODE 800        // 40 kx * 20 ky
#define NBI  1024        // B*CI
#define NBO  1024        // B*CO

// Scratch (static device globals; no runtime allocation)
__device__ float2 g_Xf[NMODE * NBI];       // [m][bi]  6.6 MB
__device__ float2 g_Yf[NBO * NMODE];       // [bo][m]  6.6 MB

// ---------------------------------------------------------------------------
// Kernel A: fused W-DFT + H-DFT for one (b,ci) image.
// Phase 1: Xw[h,ky] = sum_{w<128} (x[w] +/- x[w+128]) e^{-2pi i ky w/256}  (radix-2 fold in w)
// Phase 2: Xf[m]    = sum_{h<128} (Xw[h] +/- Xw[h+128]) e^{-2pi i kx h/256} (radix-2 fold in h)
// Thread map phase1: q=t%5 -> ky quad 4q..4q+3, rg=t/5 -> rows rg*4..rg*4+3.
// ---------------------------------------------------------------------------
__global__ void __launch_bounds__(320) stage12_fwd(const float* __restrict__ x) {
    extern __shared__ float smem[];
    float4* tws = (float4*)smem;                 // [128][5][2] float4    20480 B
    float2* xs2 = (float2*)(smem + 5120);        // [256][17] (ue,uo)     34816 B
    float2* Xws = (float2*)smem;                 // [256][20] (overlap)   40960 B
    float2* eb  = (float2*)(smem + 13824);       // e^{+2pi i t/256}       2048 B

    const int bi = blockIdx.x;
    const int t  = threadIdx.x;

    // twiddle tables
    if (t < 256) {
        float s, c;
        sincospif((float)t * (1.0f/128.0f), &s, &c);
        eb[t] = make_float2(c, s);
    }
    for (int i = t; i < 1280; i += 320) {
        int half = i & 1, q = (i >> 1) % 5, w = i / 10;
        int ky0 = 4*q + 2*half;
        float s0, c0, s1, c1;
        sincospif((float)(ky0     * w) * (1.0f/128.0f), &s0, &c0);
        sincospif((float)((ky0+1) * w) * (1.0f/128.0f), &s1, &c1);
        tws[i] = make_float4(c0, s0, c1, s1);
    }

    const int q  = t % 5;
    const int rg = t / 5;                        // 0..63 -> rows rg*4..rg*4+3
    const float* xim = x + (size_t)bi * (HH*WW);

    float aR[4][4], aI[4][4];
    #pragma unroll
    for (int r = 0; r < 4; r++)
        #pragma unroll
        for (int k = 0; k < 4; k++) { aR[r][k] = 0.f; aI[r][k] = 0.f; }

    for (int c = 0; c < 8; c++) {                // 8 chunks of 16 w (w<128)
        const int w0 = c * 16;
        __syncthreads();                          // covers table build at c==0
        for (int idx = t; idx < 4096; idx += 320) {
            int r  = idx >> 4;
            int wl = idx & 15;
            float a = xim[r*256 + w0 + wl];
            float b = xim[r*256 + w0 + wl + 128];
            xs2[r*17 + wl] = make_float2(a + b, a - b);
        }
        __syncthreads();
        #pragma unroll
        for (int wl = 0; wl < 16; wl++) {
            float4 cs0 = tws[((w0 + wl)*5 + q)*2    ];
            float4 cs1 = tws[((w0 + wl)*5 + q)*2 + 1];
            #pragma unroll
            for (int r = 0; r < 4; r++) {
                float2 u = xs2[(rg*4 + r)*17 + wl];
                aR[r][0] = fmaf( u.x, cs0.x, aR[r][0]);  // ky=4q   (even -> ue)
                aI[r][0] = fmaf(-u.x, cs0.y, aI[r][0]);
                aR[r][1] = fmaf( u.y, cs0.z, aR[r][1]);  // ky=4q+1 (odd  -> uo)
                aI[r][1] = fmaf(-u.y, cs0.w, aI[r][1]);
                aR[r][2] = fmaf( u.x, cs1.x, aR[r][2]);  // ky=4q+2
                aI[r][2] = fmaf(-u.x, cs1.y, aI[r][2]);
                aR[r][3] = fmaf( u.y, cs1.z, aR[r][3]);  // ky=4q+3
                aI[r][3] = fmaf(-u.y, cs1.w, aI[r][3]);
            }
        }
    }

    // write Xw into smem (overlaps dead tws/xs2)
    __syncthreads();
    {
        float4* X4 = (float4*)Xws;
        #pragma unroll
        for (int r = 0; r < 4; r++) {
            int base = ((rg*4 + r)*20 + 4*q) >> 1;   // float4 index, 16B aligned
            X4[base    ] = make_float4(aR[r][0], aI[r][0], aR[r][1], aI[r][1]);
            X4[base + 1] = make_float4(aR[r][2], aI[r][2], aR[r][3], aI[r][3]);
        }
    }
    __syncthreads();

    // fold along h: Xws[h] = Xw[h]+Xw[h+128], Xws[h+128] = Xw[h]-Xw[h+128]
    for (int i = t; i < 2560; i += 320) {
        float2 a = Xws[i], b = Xws[i + 2560];
        Xws[i       ] = make_float2(a.x + b.x, a.y + b.y);
        Xws[i + 2560] = make_float2(a.x - b.x, a.y - b.y);
    }
    __syncthreads();

    // Phase 2: 400 items = (j in 0..39) x (ky pair in 0..9)
    for (int it = t; it < 400; it += 320) {
        const int j   = it / 10;
        const int kyp = it % 10;
        const int kx  = (j < 20) ? j : (216 + j);
        const float4* Xp = (const float4*)(Xws + ((kx & 1) ? 2560 : 0));

        float4 acc = make_float4(0.f, 0.f, 0.f, 0.f);
        int p = 0;
        #pragma unroll 8
        for (int h = 0; h < 128; h++) {
            float2 e  = eb[p];                   // e^{+i th}; use conj
            p = (p + kx) & 255;
            float4 xv = Xp[h*10 + kyp];
            acc.x = fmaf(xv.x, e.x, acc.x); acc.x = fmaf( xv.y, e.y, acc.x);
            acc.y = fmaf(xv.y, e.x, acc.y); acc.y = fmaf(-xv.x, e.y, acc.y);
            acc.z = fmaf(xv.z, e.x, acc.z); acc.z = fmaf( xv.w, e.y, acc.z);
            acc.w = fmaf(xv.w, e.x, acc.w); acc.w = fmaf(-xv.z, e.y, acc.w);
        }
        const int m0 = j*20 + 2*kyp;
        g_Xf[(size_t)m0     * NBI + bi] = make_float2(acc.x, acc.y);
        g_Xf[(size_t)(m0+1) * NBI + bi] = make_float2(acc.z, acc.w);
    }
}

// ---------------------------------------------------------------------------
// Stage 3: channel mix, 2 modes per block (adjacent ky -> contiguous weights).
// Yf[bo,m] = sum_i Xf[m, b*64+i] * W[i,o,m]
// ---------------------------------------------------------------------------
__global__ void __launch_bounds__(256) stage3_mix(const float* __restrict__ w1re,
                                                 const float* __restrict__ w1im,
                                                 const float* __restrict__ w2re,
                                                 const float* __restrict__ w2im) {
    extern __shared__ float smem3[];
    float4* Ws  = (float4*)smem3;                 // [4096] (re0,im0,re1,im1)  64 KB
    float2* Xs0 = (float2*)(smem3 + 16384);       // [1024]                     8 KB
    float2* Xs1 = (float2*)(smem3 + 18432);       // [1024]                     8 KB

    const int bq  = blockIdx.x;                   // 0..399
    const int t   = threadIdx.x;
    const int j   = bq / 10;
    const int kyg = bq % 10;
    const int m0  = j*20 + 2*kyg;

    const float* wre; const float* wim; int off;
    if (j < 20) { wre = w1re; wim = w1im; off = j*20 + 2*kyg; }
    else        { wre = w2re; wim = w2im; off = (j-20)*20 + 2*kyg; }

    for (int io = t; io < 4096; io += 256) {
        float2 r2 = *(const float2*)(wre + (size_t)io*400 + off);
        float2 i2 = *(const float2*)(wim + (size_t)io*400 + off);
        Ws[io] = make_float4(r2.x, i2.x, r2.y, i2.y);
    }
    for (int i = t; i < 1024; i += 256) {
        Xs0[i] = g_Xf[(size_t)m0     * NBI + i];
        Xs1[i] = g_Xf[(size_t)(m0+1) * NBI + i];
    }
    __syncthreads();

    const int o  = t & 63;
    const int xb = (t >> 6) << 6;
    float a0R[4], a0I[4], a1R[4], a1I[4];
    #pragma unroll
    for (int k = 0; k < 4; k++) { a0R[k]=0.f; a0I[k]=0.f; a1R[k]=0.f; a1I[k]=0.f; }

    #pragma unroll 4
    for (int i = 0; i < 64; i++) {
        float4 wv = Ws[i*64 + o];
        #pragma unroll
        for (int k = 0; k < 4; k++) {
            float2 x0 = Xs0[xb + k*256 + i];
            a0R[k] = fmaf(x0.x, wv.x, a0R[k]); a0R[k] = fmaf(-x0.y, wv.y, a0R[k]);
            a0I[k] = fmaf(x0.x, wv.y, a0I[k]); a0I[k] = fmaf( x0.y, wv.x, a0I[k]);
            float2 x1 = Xs1[xb + k*256 + i];
            a1R[k] = fmaf(x1.x, wv.z, a1R[k]); a1R[k] = fmaf(-x1.y, wv.w, a1R[k]);
            a1I[k] = fmaf(x1.x, wv.w, a1I[k]); a1I[k] = fmaf( x1.y, wv.z, a1I[k]);
        }
    }
    float4* Y4 = (float4*)g_Yf;
    #pragma unroll
    for (int k = 0; k < 4; k++) {
        size_t base = ((size_t)(t + k*256) * NMODE + m0) >> 1;   // 16B aligned
        Y4[base] = make_float4(a0R[k], a0I[k], a1R[k], a1I[k]);
    }
}

// ---------------------------------------------------------------------------
// Kernel B: fused inverse H-DFT + c2r along W for one (b,co) image.
// Phase A: Y[h,ky] = sum_j Yf[j,ky] e^{+2pi i kx_j h/256}, radix-2 fold in h
//          via kx-parity split. Folds 1/(HW) and the c2r x2 factor.
// Phase B: out[h,w] = sum_ky (Yre cos - Yim sin), th=2pi ky w/256, with
//          w/(w+128) symmetry via even/odd-ky partial sums.
// ---------------------------------------------------------------------------
__global__ void __launch_bounds__(256) stage45_bwd(float* __restrict__ out) {
    extern __shared__ float smemb[];
    float2* Yfs = (float2*)smemb;                 // [800]                 6400 B
    float2* eb  = (float2*)(smemb + 1600);        // [256]                 2048 B
    float2* Ys  = (float2*)smemb;                 // [256][20] (overlap)  40960 B

    const int bo = blockIdx.x;
    const int t  = threadIdx.x;

    for (int i = t; i < NMODE; i += 256) Yfs[i] = g_Yf[(size_t)bo * NMODE + i];
    if (t < 256) {
        float s, c;
        sincospif((float)t * (1.0f/128.0f), &s, &c);
        eb[t] = make_float2(c, s);
    }
    __syncthreads();

    // Phase A
    {
        const int hh     = t & 127;
        const int kybase = (t >> 7) * 10;

        float aER[10], aEI[10], aOR[10], aOI[10];
        #pragma unroll
        for (int k = 0; k < 10; k++) { aER[k]=0.f; aEI[k]=0.f; aOR[k]=0.f; aOI[k]=0.f; }

        for (int j2 = 0; j2 < 20; j2++) {
            const int j0  = 2*j2;
            const int kx0 = j0 + ((j0 >= 20) ? 216 : 0);
            {   // even kx -> E accumulators
                float2 e = eb[(kx0 * hh) & 255];
                const float4* Y4 = (const float4*)(Yfs + j0*20 + kybase);
                #pragma unroll
                for (int k = 0; k < 5; k++) {
                    float4 yv = Y4[k];
                    aER[2*k  ] = fmaf(yv.x, e.x, aER[2*k  ]); aER[2*k  ] = fmaf(-yv.y, e.y, aER[2*k  ]);
                    aEI[2*k  ] = fmaf(yv.x, e.y, aEI[2*k  ]); aEI[2*k  ] = fmaf( yv.y, e.x, aEI[2*k  ]);
                    aER[2*k+1] = fmaf(yv.z, e.x, aER[2*k+1]); aER[2*k+1] = fmaf(-yv.w, e.y, aER[2*k+1]);
                    aEI[2*k+1] = fmaf(yv.z, e.y, aEI[2*k+1]); aEI[2*k+1] = fmaf( yv.w, e.x, aEI[2*k+1]);
                }
            }
            {   // odd kx -> O accumulators
                float2 e = eb[((kx0+1) * hh) & 255];
                const float4* Y4 = (const float4*)(Yfs + (j0+1)*20 + kybase);
                #pragma unroll
                for (int k = 0; k < 5; k++) {
                    float4 yv = Y4[k];
                    aOR[2*k  ] = fmaf(yv.x, e.x, aOR[2*k  ]); aOR[2*k  ] = fmaf(-yv.y, e.y, aOR[2*k  ]);
                    aOI[2*k  ] = fmaf(yv.x, e.y, aOI[2*k  ]); aOI[2*k  ] = fmaf( yv.y, e.x, aOI[2*k  ]);
                    aOR[2*k+1] = fmaf(yv.z, e.x, aOR[2*k+1]); aOR[2*k+1] = fmaf(-yv.w, e.y, aOR[2*k+1]);
                    aOI[2*k+1] = fmaf(yv.z, e.y, aOI[2*k+1]); aOI[2*k+1] = fmaf( yv.w, e.x, aOI[2*k+1]);
                }
            }
        }

        __syncthreads();   // all Yfs/eb reads done before Ys overwrite
        const float sc1 = 1.0f / 65536.0f;
        const float sc2 = 2.0f / 65536.0f;
        #pragma unroll
        for (int k = 0; k < 10; k++) {
            int ky  = kybase + k;
            float s = (ky == 0) ? sc1 : sc2;
            Ys[ hh       *20 + ky] = make_float2((aER[k] + aOR[k])*s, (aEI[k] + aOI[k])*s);
            Ys[(hh + 128)*20 + ky] = make_float2((aER[k] - aOR[k])*s, (aEI[k] - aOI[k])*s);
        }
        __syncthreads();
    }

    // Phase B
    {
        const int w    = t & 127;
        const int half = t >> 7;

        float cc[20], ns[20];
        #pragma unroll
        for (int ky = 0; ky < 20; ky++) {
            float s, c;
            sincospif((float)(ky * w) * (1.0f/128.0f), &s, &c);
            cc[ky] = c; ns[ky] = -s;
        }

        float* outb = out + (size_t)bo * (HH*WW);
        const float4* y4 = (const float4*)Ys;

        for (int rr = 0; rr < 128; rr++) {
            const int r = half*128 + rr;
            float ae = 0.f, ao = 0.f;
            #pragma unroll
            for (int kk = 0; kk < 10; kk++) {
                float4 yv = y4[r*10 + kk];       // (re_e, im_e, re_o, im_o)
                ae = fmaf(yv.x, cc[2*kk  ], ae); ae = fmaf(yv.y, ns[2*kk  ], ae);
                ao = fmaf(yv.z, cc[2*kk+1], ao); ao = fmaf(yv.w, ns[2*kk+1], ao);
            }
            outb[r*256 + w      ] = ae + ao;
            outb[r*256 + w + 128] = ae - ao;
        }
    }
}

// ---------------------------------------------------------------------------
extern "C" void kernel_launch(void* const* d_in, const int* in_sizes, int n_in,
                              void* d_out, int out_size) {
    const float* x    = (const float*)d_in[0];
    const float* w1re = (const float*)d_in[1];
    const float* w1im = (const float*)d_in[2];
    const float* w2re = (const float*)d_in[3];
    const float* w2im = (const float*)d_in[4];
    float* out = (float*)d_out;

    const int sA = 57344;   // tws+xs2 (55296) + eb (2048); Xws overlaps [0,40960)
    const int s3 = 81920;   // Ws 64K + Xs0/Xs1 16K
    const int sB = 40960;   // Ys; Yfs+eb overlap at front
    cudaFuncSetAttribute(stage12_fwd, cudaFuncAttributeMaxDynamicSharedMemorySize, sA);
    cudaFuncSetAttribute(stage3_mix,  cudaFuncAttributeMaxDynamicSharedMemorySize, s3);
    cudaFuncSetAttribute(stage45_bwd, cudaFuncAttributeMaxDynamicSharedMemorySize, sB);

    stage12_fwd<<<NBI, 320, sA>>>(x);
    stage3_mix <<<400, 256, s3>>>(w1re, w1im, w2re, w2im);
    stage45_bwd<<<NBO, 256, sB>>>(out);
}

// round 3
// speedup vs baseline: 1.4961x; 1.1434x over previous
#include <cuda_runtime.h>
#include <math.h>

#define BB   16
#define CIN  64
#define COUT 64
#define HH   256
#define WW   256
#define NMODE 800        // 40 kx * 20 ky
#define NBI  1024        // B*CI
#define NBO  1024        // B*CO

__device__ float2 g_Xf[NMODE * NBI];       // [m][bi]  6.6 MB
__device__ float2 g_Yf[NBO * NMODE];       // [bo][m]  6.6 MB

// ---------------------------------------------------------------------------
// Kernel A: fused W-DFT + H-DFT for one (b,ci) image. 256 threads.
// Phase 1: thread = (ky-quarter q = t>>6 -> ky 5q..5q+4, rowgroup rg = t&63 ->
//          rows rg+64r). Twiddle loads are warp-uniform broadcasts.
//          Radix-2 fold in w (ue/uo) and, at the end, in h (rows r / r+128).
// Phase 2: 400 (j,kypair) items over 256 threads, h<128 with parity buffers.
// smem (floats):
//   tw   [0,5120)      128 wl x 20 ky x (c,s)
//   xse  [5120,10240)  256 rows x 5 float4 (pitch 5) even fold
//   xso  [10240,15360) odd fold
//   eb   [15360,15872) e^{+2pi i t/256}
//   Xsum [0,5120)   / Xdif [5120,10240)   (phase-2 inputs, overlap tw/xse)
// ---------------------------------------------------------------------------
template<int QP>
__device__ __forceinline__ void p1_accum(
    const float (&ue)[4][4], const float (&uo)[4][4],
    const float* __restrict__ smem, int wl, int ky0,
    float (&aR)[5][4], float (&aI)[5][4])
{
    const float2* tw2 = (const float2*)smem;
    #pragma unroll
    for (int k = 0; k < 5; k++) {
        float2 cs = tw2[wl*20 + ky0 + k];        // warp-uniform -> broadcast
        const bool odd = ((QP + k) & 1) != 0;
        #pragma unroll
        for (int r = 0; r < 4; r++) {
            // wc handled by caller: this is invoked once per wc with ue/uo cols
            // (see call site: we pass per-wc slices) -- actually full 4x here:
        }
        // NOTE: real accumulation below in caller macro style
        (void)cs; (void)odd;
    }
}

__global__ void __launch_bounds__(256, 2) stage12_fwd(const float* __restrict__ x) {
    extern __shared__ float smem[];
    float2* tw2  = (float2*)smem;                  // [128][20]
    float4* xse4 = (float4*)(smem + 5120);         // [256][5]
    float4* xso4 = (float4*)(smem + 10240);        // [256][5]
    float2* eb   = (float2*)(smem + 15360);        // [256]

    const int bi = blockIdx.x;
    const int t  = threadIdx.x;

    // twiddle tables
    for (int i = t; i < 2560; i += 256) {
        int wl = i / 20, ky = i % 20;
        float s, c;
        sincospif((float)(ky * wl) * (1.0f/128.0f), &s, &c);
        tw2[i] = make_float2(c, s);
    }
    {
        float s, c;
        sincospif((float)t * (1.0f/128.0f), &s, &c);
        eb[t] = make_float2(c, s);
    }

    const int q   = t >> 6;        // ky quarter (warp-uniform)
    const int rg  = t & 63;
    const int ky0 = 5 * q;
    const int qp  = q & 1;         // parity of ky0
    const float4* Xg4 = (const float4*)(x + (size_t)bi * (HH*WW));

    float aR[5][4], aI[5][4];
    #pragma unroll
    for (int k = 0; k < 5; k++)
        #pragma unroll
        for (int r = 0; r < 4; r++) { aR[k][r] = 0.f; aI[k][r] = 0.f; }

    for (int c = 0; c < 8; c++) {              // chunks of 16 w (w<128)
        const int w04 = c * 4;                 // float4 offset of w0
        __syncthreads();
        #pragma unroll
        for (int it = 0; it < 4; it++) {
            int idx = t + it*256;              // 0..1023
            int r   = idx >> 2;
            int wl4 = idx & 3;
            float4 a = Xg4[r*64 + w04 + wl4];
            float4 b = Xg4[r*64 + w04 + wl4 + 32];
            xse4[r*5 + wl4] = make_float4(a.x+b.x, a.y+b.y, a.z+b.z, a.w+b.w);
            xso4[r*5 + wl4] = make_float4(a.x-b.x, a.y-b.y, a.z-b.z, a.w-b.w);
        }
        __syncthreads();

        #pragma unroll
        for (int wl4 = 0; wl4 < 4; wl4++) {
            float ue[4][4], uo[4][4];
            #pragma unroll
            for (int r = 0; r < 4; r++) {
                float4 e = xse4[(rg + 64*r)*5 + wl4];
                float4 o = xso4[(rg + 64*r)*5 + wl4];
                ue[r][0]=e.x; ue[r][1]=e.y; ue[r][2]=e.z; ue[r][3]=e.w;
                uo[r][0]=o.x; uo[r][1]=o.y; uo[r][2]=o.z; uo[r][3]=o.w;
            }
            #pragma unroll
            for (int wc = 0; wc < 4; wc++) {
                const int wl = c*16 + wl4*4 + wc;
                #pragma unroll
                for (int k = 0; k < 5; k++) {
                    float2 cs = tw2[wl*20 + ky0 + k];   // broadcast
                    if (((qp + k) & 1) == 0) {
                        #pragma unroll
                        for (int r = 0; r < 4; r++) {
                            aR[k][r] = fmaf( ue[r][wc], cs.x, aR[k][r]);
                            aI[k][r] = fmaf(-ue[r][wc], cs.y, aI[k][r]);
                        }
                    } else {
                        #pragma unroll
                        for (int r = 0; r < 4; r++) {
                            aR[k][r] = fmaf( uo[r][wc], cs.x, aR[k][r]);
                            aI[k][r] = fmaf(-uo[r][wc], cs.y, aI[k][r]);
                        }
                    }
                }
            }
        }
    }

    // h-fold in registers, write phase-2 buffers (overlap tw/xse)
    __syncthreads();
    {
        float2* Xsum = (float2*)smem;          // [128][20]
        float2* Xdif = Xsum + 2560;
        #pragma unroll
        for (int k = 0; k < 5; k++) {
            // rows: r=0 -> rg, r=1 -> rg+64, r=2 -> rg+128, r=3 -> rg+192
            Xsum[rg*20 + ky0 + k]      = make_float2(aR[k][0]+aR[k][2], aI[k][0]+aI[k][2]);
            Xdif[rg*20 + ky0 + k]      = make_float2(aR[k][0]-aR[k][2], aI[k][0]-aI[k][2]);
            Xsum[(rg+64)*20 + ky0 + k] = make_float2(aR[k][1]+aR[k][3], aI[k][1]+aI[k][3]);
            Xdif[(rg+64)*20 + ky0 + k] = make_float2(aR[k][1]-aR[k][3], aI[k][1]-aI[k][3]);
        }
    }
    __syncthreads();

    // Phase 2
    const float4* base4 = (const float4*)smem;
    for (int it = t; it < 400; it += 256) {
        const int j   = it / 10;
        const int kp  = it % 10;
        const int kx  = (j < 20) ? j : (216 + j);
        const float4* Xp = base4 + ((kx & 1) ? 1280 : 0);

        float4 acc = make_float4(0.f, 0.f, 0.f, 0.f);
        int p = 0;
        #pragma unroll 8
        for (int h = 0; h < 128; h++) {
            float2 e  = eb[p];                  // e^{+i th}; use conj
            p = (p + kx) & 255;
            float4 xv = Xp[h*10 + kp];
            acc.x = fmaf(xv.x, e.x, acc.x); acc.x = fmaf( xv.y, e.y, acc.x);
            acc.y = fmaf(xv.y, e.x, acc.y); acc.y = fmaf(-xv.x, e.y, acc.y);
            acc.z = fmaf(xv.z, e.x, acc.z); acc.z = fmaf( xv.w, e.y, acc.z);
            acc.w = fmaf(xv.w, e.x, acc.w); acc.w = fmaf(-xv.z, e.y, acc.w);
        }
        const int m0 = j*20 + 2*kp;
        g_Xf[(size_t)m0     * NBI + bi] = make_float2(acc.x, acc.y);
        g_Xf[(size_t)(m0+1) * NBI + bi] = make_float2(acc.z, acc.w);
    }
}

// ---------------------------------------------------------------------------
// Stage 3: channel mix, 2 modes per block. (unchanged from R2)
// ---------------------------------------------------------------------------
__global__ void __launch_bounds__(256) stage3_mix(const float* __restrict__ w1re,
                                                 const float* __restrict__ w1im,
                                                 const float* __restrict__ w2re,
                                                 const float* __restrict__ w2im) {
    extern __shared__ float smem3[];
    float4* Ws  = (float4*)smem3;                 // [4096]
    float2* Xs0 = (float2*)(smem3 + 16384);       // [1024]
    float2* Xs1 = (float2*)(smem3 + 18432);       // [1024]

    const int bq  = blockIdx.x;                   // 0..399
    const int t   = threadIdx.x;
    const int j   = bq / 10;
    const int kyg = bq % 10;
    const int m0  = j*20 + 2*kyg;

    const float* wre; const float* wim; int off;
    if (j < 20) { wre = w1re; wim = w1im; off = j*20 + 2*kyg; }
    else        { wre = w2re; wim = w2im; off = (j-20)*20 + 2*kyg; }

    for (int io = t; io < 4096; io += 256) {
        float2 r2 = *(const float2*)(wre + (size_t)io*400 + off);
        float2 i2 = *(const float2*)(wim + (size_t)io*400 + off);
        Ws[io] = make_float4(r2.x, i2.x, r2.y, i2.y);
    }
    for (int i = t; i < 1024; i += 256) {
        Xs0[i] = g_Xf[(size_t)m0     * NBI + i];
        Xs1[i] = g_Xf[(size_t)(m0+1) * NBI + i];
    }
    __syncthreads();

    const int o  = t & 63;
    const int xb = (t >> 6) << 6;
    float a0R[4], a0I[4], a1R[4], a1I[4];
    #pragma unroll
    for (int k = 0; k < 4; k++) { a0R[k]=0.f; a0I[k]=0.f; a1R[k]=0.f; a1I[k]=0.f; }

    #pragma unroll 4
    for (int i = 0; i < 64; i++) {
        float4 wv = Ws[i*64 + o];
        #pragma unroll
        for (int k = 0; k < 4; k++) {
            float2 x0 = Xs0[xb + k*256 + i];
            a0R[k] = fmaf(x0.x, wv.x, a0R[k]); a0R[k] = fmaf(-x0.y, wv.y, a0R[k]);
            a0I[k] = fmaf(x0.x, wv.y, a0I[k]); a0I[k] = fmaf( x0.y, wv.x, a0I[k]);
            float2 x1 = Xs1[xb + k*256 + i];
            a1R[k] = fmaf(x1.x, wv.z, a1R[k]); a1R[k] = fmaf(-x1.y, wv.w, a1R[k]);
            a1I[k] = fmaf(x1.x, wv.w, a1I[k]); a1I[k] = fmaf( x1.y, wv.z, a1I[k]);
        }
    }
    float4* Y4 = (float4*)g_Yf;
    #pragma unroll
    for (int k = 0; k < 4; k++) {
        size_t base = ((size_t)(t + k*256) * NMODE + m0) >> 1;
        Y4[base] = make_float4(a0R[k], a0I[k], a1R[k], a1I[k]);
    }
}

// ---------------------------------------------------------------------------
// Kernel B: fused inverse H-DFT + c2r. 256 threads.
// Phase A: as R2 (kx-parity fold in h), writes Ys[256][20] float2 (scaled).
// Phase B: thread = (w = t&63, r-quarter = t>>6). Per r: 6 accumulators
//          (P0..P3,Q1,Q3) by ky mod 4 give out[w], out[w+64], out[w+128],
//          out[w+192] from 60 FMA. All yv LDS are warp-broadcasts.
// ---------------------------------------------------------------------------
__global__ void __launch_bounds__(256, 2) stage45_bwd(float* __restrict__ out) {
    extern __shared__ float smemb[];
    float2* Yfs = (float2*)smemb;                 // [800]
    float2* eb  = (float2*)(smemb + 1600);        // [256]
    float2* Ys  = (float2*)smemb;                 // [256][20] (overlap)

    const int bo = blockIdx.x;
    const int t  = threadIdx.x;

    for (int i = t; i < NMODE; i += 256) Yfs[i] = g_Yf[(size_t)bo * NMODE + i];
    {
        float s, c;
        sincospif((float)t * (1.0f/128.0f), &s, &c);
        eb[t] = make_float2(c, s);
    }
    __syncthreads();

    // Phase A
    {
        const int hh     = t & 127;
        const int kybase = (t >> 7) * 10;

        float aER[10], aEI[10], aOR[10], aOI[10];
        #pragma unroll
        for (int k = 0; k < 10; k++) { aER[k]=0.f; aEI[k]=0.f; aOR[k]=0.f; aOI[k]=0.f; }

        for (int j2 = 0; j2 < 20; j2++) {
            const int j0  = 2*j2;
            const int kx0 = j0 + ((j0 >= 20) ? 216 : 0);
            {
                float2 e = eb[(kx0 * hh) & 255];
                const float4* Y4 = (const float4*)(Yfs + j0*20 + kybase);
                #pragma unroll
                for (int k = 0; k < 5; k++) {
                    float4 yv = Y4[k];
                    aER[2*k  ] = fmaf(yv.x, e.x, aER[2*k  ]); aER[2*k  ] = fmaf(-yv.y, e.y, aER[2*k  ]);
                    aEI[2*k  ] = fmaf(yv.x, e.y, aEI[2*k  ]); aEI[2*k  ] = fmaf( yv.y, e.x, aEI[2*k  ]);
                    aER[2*k+1] = fmaf(yv.z, e.x, aER[2*k+1]); aER[2*k+1] = fmaf(-yv.w, e.y, aER[2*k+1]);
                    aEI[2*k+1] = fmaf(yv.z, e.y, aEI[2*k+1]); aEI[2*k+1] = fmaf( yv.w, e.x, aEI[2*k+1]);
                }
            }
            {
                float2 e = eb[((kx0+1) * hh) & 255];
                const float4* Y4 = (const float4*)(Yfs + (j0+1)*20 + kybase);
                #pragma unroll
                for (int k = 0; k < 5; k++) {
                    float4 yv = Y4[k];
                    aOR[2*k  ] = fmaf(yv.x, e.x, aOR[2*k  ]); aOR[2*k  ] = fmaf(-yv.y, e.y, aOR[2*k  ]);
                    aOI[2*k  ] = fmaf(yv.x, e.y, aOI[2*k  ]); aOI[2*k  ] = fmaf( yv.y, e.x, aOI[2*k  ]);
                    aOR[2*k+1] = fmaf(yv.z, e.x, aOR[2*k+1]); aOR[2*k+1] = fmaf(-yv.w, e.y, aOR[2*k+1]);
                    aOI[2*k+1] = fmaf(yv.z, e.y, aOI[2*k+1]); aOI[2*k+1] = fmaf( yv.w, e.x, aOI[2*k+1]);
                }
            }
        }

        __syncthreads();
        const float sc1 = 1.0f / 65536.0f;
        const float sc2 = 2.0f / 65536.0f;
        #pragma unroll
        for (int k = 0; k < 10; k++) {
            int ky  = kybase + k;
            float s = (ky == 0) ? sc1 : sc2;
            Ys[ (t & 127)       *20 + ky] = make_float2((aER[k] + aOR[k])*s, (aEI[k] + aOI[k])*s);
            Ys[((t & 127) + 128)*20 + ky] = make_float2((aER[k] - aOR[k])*s, (aEI[k] - aOI[k])*s);
        }
        __syncthreads();
    }

    // Phase B
    {
        const int w  = t & 63;
        const int qr = t >> 6;

        float cc[20], ss[20];
        #pragma unroll
        for (int ky = 0; ky < 20; ky++) {
            float s, c;
            sincospif((float)(ky * w) * (1.0f/128.0f), &s, &c);
            cc[ky] = c; ss[ky] = s;
        }

        float* outb = out + (size_t)bo * (HH*WW);
        const float4* y4 = (const float4*)Ys;

        #pragma unroll 2
        for (int rr = 0; rr < 64; rr++) {
            const int r = qr*64 + rr;
            float P0=0.f, P1=0.f, P2=0.f, P3=0.f, Q1=0.f, Q3=0.f;
            #pragma unroll
            for (int qq = 0; qq < 5; qq++) {
                {   // float4 index 2qq: ky pair (4qq, 4qq+1) -> classes 0,1
                    float4 yv = y4[r*10 + 2*qq];
                    const int k0 = 4*qq, k1 = 4*qq + 1;
                    P0 = fmaf(yv.x, cc[k0], P0); P0 = fmaf(-yv.y, ss[k0], P0);
                    P1 = fmaf(yv.z, cc[k1], P1); P1 = fmaf(-yv.w, ss[k1], P1);
                    Q1 = fmaf(yv.z, ss[k1], Q1); Q1 = fmaf( yv.w, cc[k1], Q1);
                }
                {   // float4 index 2qq+1: ky pair (4qq+2, 4qq+3) -> classes 2,3
                    float4 yv = y4[r*10 + 2*qq + 1];
                    const int k2 = 4*qq + 2, k3 = 4*qq + 3;
                    P2 = fmaf(yv.x, cc[k2], P2); P2 = fmaf(-yv.y, ss[k2], P2);
                    P3 = fmaf(yv.z, cc[k3], P3); P3 = fmaf(-yv.w, ss[k3], P3);
                    Q3 = fmaf(yv.z, ss[k3], Q3); Q3 = fmaf( yv.w, cc[k3], Q3);
                }
            }
            outb[r*256 + w      ] = P0 + P1 + P2 + P3;
            outb[r*256 + w +  64] = P0 - Q1 - P2 + Q3;
            outb[r*256 + w + 128] = P0 - P1 + P2 - P3;
            outb[r*256 + w + 192] = P0 + Q1 - P2 - Q3;
        }
    }
}

// ---------------------------------------------------------------------------
extern "C" void kernel_launch(void* const* d_in, const int* in_sizes, int n_in,
                              void* d_out, int out_size) {
    const float* x    = (const float*)d_in[0];
    const float* w1re = (const float*)d_in[1];
    const float* w1im = (const float*)d_in[2];
    const float* w2re = (const float*)d_in[3];
    const float* w2im = (const float*)d_in[4];
    float* out = (float*)d_out;

    const int sA = 63488;   // tw+xse+xso+eb; Xsum/Xdif overlap
    const int s3 = 81920;
    const int sB = 40960;   // Ys; Yfs+eb overlap at front
    cudaFuncSetAttribute(stage12_fwd, cudaFuncAttributeMaxDynamicSharedMemorySize, sA);
    cudaFuncSetAttribute(stage3_mix,  cudaFuncAttributeMaxDynamicSharedMemorySize, s3);
    cudaFuncSetAttribute(stage45_bwd, cudaFuncAttributeMaxDynamicSharedMemorySize, sB);

    stage12_fwd<<<NBI, 256, sA>>>(x);
    stage3_mix <<<400, 256, s3>>>(w1re, w1im, w2re, w2im);
    stage45_bwd<<<NBO, 256, sB>>>(out);
}